// round 13
// baseline (speedup 1.0000x reference)
#include <cuda_runtime.h>
#include <cstdint>

#define BB   32
#define TT   336
#define NH   100
#define NM   150
#define FH   8
#define FM   16
#define HG   64
#define HL   64
#define FUT  24
#define TCB  16          // timesteps per producer block
#define TF   8           // timesteps per flag granule
#define NCK  (TT / TF)   // 42 flag granules
#define TB   16          // graphs per gnn block

// GNN output x: [n][t][b][hg]
__device__ float g_x[(size_t)NH * TT * BB * HG];
// Precomputed x-gates (+bias): [n][t][b][256]
__device__ float g_gates[(size_t)NH * TT * BB * 256];
// producer->consumer readiness flags, one per (node, 8-step granule)
__device__ int d_flag[NH * NCK];

// CSR edge structure (built once per launch, deterministic order)
__device__ int d_off_h[NH], d_deg_h[NH], d_src_h[512];
__device__ int d_off_m[NH], d_deg_m[NH], d_src_m[1024];

// ---------------------------------------------------------------------------
// Kernel A0: build CSR by target node; also zero the handshake flags.
// ---------------------------------------------------------------------------
__global__ void __launch_bounds__(256) csr_kernel(
    const int* __restrict__ eh, const int* __restrict__ em, int Eh, int Em)
{
    __shared__ int s_src[1024], s_tgt[1024];
    const int tid = threadIdx.x;

    for (int i = tid; i < NH * NCK; i += 256) d_flag[i] = 0;

    for (int i = tid; i < Eh; i += 256) { s_src[i] = eh[i]; s_tgt[i] = eh[Eh + i]; }
    __syncthreads();
    if (tid < NH) {
        int start = 0;
        for (int e = 0; e < Eh; e++) start += (s_tgt[e] < tid) ? 1 : 0;
        int p = start, cnt = 0;
        for (int e = 0; e < Eh; e++)
            if (s_tgt[e] == tid) { d_src_h[p++] = s_src[e]; cnt++; }
        d_off_h[tid] = start; d_deg_h[tid] = cnt;
    }
    __syncthreads();
    for (int i = tid; i < Em; i += 256) { s_src[i] = em[i]; s_tgt[i] = em[Em + i]; }
    __syncthreads();
    if (tid < NH) {
        int start = 0;
        for (int e = 0; e < Em; e++) start += (s_tgt[e] < tid) ? 1 : 0;
        int p = start, cnt = 0;
        for (int e = 0; e < Em; e++)
            if (s_tgt[e] == tid) { d_src_m[p++] = s_src[e]; cnt++; }
        d_off_m[tid] = start; d_deg_m[tid] = cnt;
    }
}

// ---------------------------------------------------------------------------
// Kernel A: hetero GraphConv, TB graphs per block, CSR gather. (R6, verified)
// ---------------------------------------------------------------------------
__global__ void __launch_bounds__(256) gnn_kernel(
    const float* __restrict__ xm_all, const float* __restrict__ xh_all,
    const float* __restrict__ Wrel_m, const float* __restrict__ brel_m,
    const float* __restrict__ Wroot_m,
    const float* __restrict__ Wrel_h, const float* __restrict__ brel_h,
    const float* __restrict__ Wroot_h)
{
    __shared__ float swh[FH * HG];
    __shared__ float swr[FH * HG];
    __shared__ float swm[FM * HG];
    __shared__ float sb[HG];
    __shared__ int soff_h[NH], sdeg_h[NH], ssrc_h[512];
    __shared__ int soff_m[NH], sdeg_m[NH], ssrc_m[1024];
    __shared__ float sxh[NH * FH];
    __shared__ float sxm[NM * FM];
    __shared__ float sah[NH * FH];
    __shared__ float sam[NH * FM];

    const int tid = threadIdx.x;

    for (int i = tid; i < HG * FH; i += 256) {
        int j = i / FH, k = i % FH;
        swh[k * HG + j] = 0.5f * Wrel_h[i];
        swr[k * HG + j] = 0.5f * (Wroot_h[i] + Wroot_m[i]);
    }
    for (int i = tid; i < HG * FM; i += 256) {
        int j = i / FM, k = i % FM;
        swm[k * HG + j] = 0.5f * Wrel_m[i];
    }
    for (int i = tid; i < HG; i += 256) sb[i] = 0.5f * (brel_h[i] + brel_m[i]);
    for (int i = tid; i < NH; i += 256) {
        soff_h[i] = d_off_h[i]; sdeg_h[i] = d_deg_h[i];
        soff_m[i] = d_off_m[i]; sdeg_m[i] = d_deg_m[i];
    }
    for (int i = tid; i < 512;  i += 256) ssrc_h[i] = d_src_h[i];
    for (int i = tid; i < 1024; i += 256) ssrc_m[i] = d_src_m[i];

    for (int gi = 0; gi < TB; gi++) {
        const int g = blockIdx.x * TB + gi;
        const float* xh = xh_all + (size_t)g * NH * FH;
        const float* xm = xm_all + (size_t)g * NM * FM;

        __syncthreads();
        for (int i = tid; i < NH * FH / 4; i += 256)
            *(float4*)&sxh[i * 4] = *(const float4*)&xh[i * 4];
        for (int i = tid; i < NM * FM / 4; i += 256)
            *(float4*)&sxm[i * 4] = *(const float4*)&xm[i * 4];
        __syncthreads();

        for (int idx = tid; idx < NH * FH; idx += 256) {
            int n = idx >> 3, k = idx & 7;
            int o = soff_h[n], d = sdeg_h[n];
            float s = 0.f;
            for (int e = 0; e < d; e++) s += sxh[ssrc_h[o + e] * FH + k];
            sah[idx] = s;
        }
        for (int idx = tid; idx < NH * FM; idx += 256) {
            int n = idx >> 4, k = idx & 15;
            int o = soff_m[n], d = sdeg_m[n];
            float s = 0.f;
            for (int e = 0; e < d; e++) s += sxm[ssrc_m[o + e] * FM + k];
            sam[idx] = s;
        }
        __syncthreads();

        const int t = g % TT;
        const int b = g / TT;
        for (int idx = tid; idx < NH * HG; idx += 256) {
            int n = idx >> 6, j = idx & 63;
            float acc = sb[j];
            #pragma unroll
            for (int k = 0; k < FH; k++)
                acc += sah[n * FH + k] * swh[k * HG + j]
                     + sxh[n * FH + k] * swr[k * HG + j];
            #pragma unroll
            for (int k = 0; k < FM; k++)
                acc += sam[n * FM + k] * swm[k * HG + j];
            float v = acc > 0.f ? acc : 0.01f * acc;
            g_x[(((size_t)n * TT + t) * BB + b) * HG + j] = v;
        }
    }
}

// ---------------------------------------------------------------------------
// FUSED kernel: blockIdx < NH  -> LSTM consumer role
//               blockIdx >= NH -> xgemm producer role, one (node, 16-step
//                                 block) each, chunk-major; publishes TWO
//                                 flags (after step 8 and step 16).
// ---------------------------------------------------------------------------
#define O_WHH 0
#define O_HL  16384
#define O_WL  (O_HL + 64*33)
#define O_BL  (O_WL + 24*64)
#define LS_FLOATS (O_BL + 32)
#define XG_SW 0
#define XG_SB 16384
#define XG_SX (16384 + 256)
#define XG_FLOATS (XG_SX + 64*33)
#define FUSED_FLOATS (LS_FLOATS > XG_FLOATS ? LS_FLOATS : XG_FLOATS)
#define FUSED_BYTES  (FUSED_FLOATS * 4)

__device__ __forceinline__ float sigm(float x) {
    return 1.0f / (1.0f + __expf(-x));
}
__device__ __forceinline__ float tanh_fast(float x) {
    float xc = fminf(fmaxf(x, -15.f), 15.f);
    float e = __expf(2.0f * xc);
    return (e - 1.0f) / (e + 1.0f);
}
__device__ __forceinline__ void wait_flag(const int* f) {
    int v;
    for (;;) {
        asm volatile("ld.acquire.gpu.s32 %0, [%1];" : "=r"(v) : "l"(f) : "memory");
        if (v) break;
        __nanosleep(200);
    }
}

__global__ void __launch_bounds__(256) fused_kernel(
    const float* __restrict__ W_ih, const float* __restrict__ W_hh,
    const float* __restrict__ b_ih, const float* __restrict__ b_hh,
    const float* __restrict__ W_lin, const float* __restrict__ b_lin,
    float* __restrict__ out)
{
    extern __shared__ float sm[];
    const int tid = threadIdx.x;

    if (blockIdx.x >= NH) {
        // ----------------- producer role: xgemm for (n, 16-step blk) --------
        const int id = blockIdx.x - NH;
        const int cb = id / NH;          // block-chunk major: all nodes first
        const int n  = id % NH;
        const int t0 = cb * TCB;

        float* sW = sm + XG_SW;
        float* sb = sm + XG_SB;
        float* sx = sm + XG_SX;

        const float* w = W_ih + (size_t)n * 256 * 64;
        for (int i = tid; i < 16384; i += 256) {
            int j = i >> 6, k = i & 63;
            sW[k * 256 + j] = w[i];
        }
        sb[tid] = b_ih[n * 256 + tid] + b_hh[n * 256 + tid];

        const int tm = tid >> 5;
        const int tn = tid & 31;
        const int sb_b = tid >> 3;
        const int sb_k = (tid & 7) << 3;

        const float* xbase = g_x + ((size_t)n * TT + t0) * BB * HG;
        float* gbase = g_gates + ((size_t)n * TT + t0) * BB * 256;
        __syncthreads();

        for (int tt = 0; tt < TCB; tt++) {
            const float* xt = xbase + (size_t)tt * BB * HG;
            float4 v0 = *(const float4*)&xt[sb_b * HG + sb_k];
            float4 v1 = *(const float4*)&xt[sb_b * HG + sb_k + 4];
            sx[(sb_k + 0) * 33 + sb_b] = v0.x;
            sx[(sb_k + 1) * 33 + sb_b] = v0.y;
            sx[(sb_k + 2) * 33 + sb_b] = v0.z;
            sx[(sb_k + 3) * 33 + sb_b] = v0.w;
            sx[(sb_k + 4) * 33 + sb_b] = v1.x;
            sx[(sb_k + 5) * 33 + sb_b] = v1.y;
            sx[(sb_k + 6) * 33 + sb_b] = v1.z;
            sx[(sb_k + 7) * 33 + sb_b] = v1.w;
            __syncthreads();

            float acc[4][8];
            #pragma unroll
            for (int mi = 0; mi < 4; mi++)
                #pragma unroll
                for (int gg = 0; gg < 4; gg++) {
                    acc[mi][gg * 2 + 0] = sb[gg * 64 + 2 * tn + 0];
                    acc[mi][gg * 2 + 1] = sb[gg * 64 + 2 * tn + 1];
                }

            #pragma unroll 4
            for (int k = 0; k < 64; k++) {
                float xv[4];
                #pragma unroll
                for (int mi = 0; mi < 4; mi++) xv[mi] = sx[k * 33 + 4 * tm + mi];
                #pragma unroll
                for (int gg = 0; gg < 4; gg++) {
                    float2 wv = *(const float2*)&sW[k * 256 + gg * 64 + 2 * tn];
                    #pragma unroll
                    for (int mi = 0; mi < 4; mi++) {
                        acc[mi][gg * 2 + 0] += xv[mi] * wv.x;
                        acc[mi][gg * 2 + 1] += xv[mi] * wv.y;
                    }
                }
            }

            float* gt = gbase + (size_t)tt * BB * 256;
            #pragma unroll
            for (int mi = 0; mi < 4; mi++)
                #pragma unroll
                for (int gg = 0; gg < 4; gg++) {
                    float2 v; v.x = acc[mi][gg * 2]; v.y = acc[mi][gg * 2 + 1];
                    *(float2*)&gt[(4 * tm + mi) * 256 + gg * 64 + 2 * tn] = v;
                }
            __syncthreads();   // stores of step tt visible block-wide

            // publish 8-step granules early (after tt=7) and at the end
            if ((tt == TF - 1 || tt == TCB - 1) && tid == 0) {
                __threadfence();
                atomicExch(&d_flag[n * NCK + cb * 2 + (tt >> 3)], 1);
            }
        }
        return;
    }

    // ------------------- consumer role: LSTM for node n ---------------------
    const int n  = blockIdx.x;
    const int tm = tid >> 5;   // warp = batch group 4tm..4tm+3
    const int tn = tid & 31;   // lane = unit pair {2tn, 2tn+1}

    float* sWhh  = sm + O_WHH;   // [k][j] stride 256
    float* shl   = sm + O_HL;    // h_last [u][b] stride 33
    float* sWlin = sm + O_WL;
    float* sblin = sm + O_BL;

    const float* whh = W_hh + (size_t)n * 256 * 64;
    for (int i = tid; i < 16384; i += 256) {
        int j = i >> 6, k = i & 63;
        sWhh[k * 256 + j] = whh[i];
    }
    for (int i = tid; i < FUT * HL; i += 256) sWlin[i] = W_lin[i];
    if (tid < FUT) sblin[tid] = b_lin[tid];
    __syncthreads();   // weights visible; no more block syncs until the tail

    const int* flg = &d_flag[n * NCK];

    float h0[4], h1[4], c[4][2];
    #pragma unroll
    for (int mi = 0; mi < 4; mi++) {
        h0[mi] = 0.f; h1[mi] = 0.f;
        c[mi][0] = 0.f; c[mi][1] = 0.f;
    }

    const float* gptr = g_gates + (size_t)n * TT * BB * 256;

    // wait for granule 0, then prefetch gates(t=0)
    wait_flag(&flg[0]);
    float gb[4][8];
    #pragma unroll
    for (int mi = 0; mi < 4; mi++)
        #pragma unroll
        for (int gg = 0; gg < 4; gg++) {
            float2 v = *(const float2*)&gptr[(4 * tm + mi) * 256 + gg * 64 + 2 * tn];
            gb[mi][gg * 2] = v.x; gb[mi][gg * 2 + 1] = v.y;
        }

    for (int t = 0; t < TT; t++) {
        float acc[4][8];
        #pragma unroll
        for (int mi = 0; mi < 4; mi++)
            #pragma unroll
            for (int q = 0; q < 8; q++) acc[mi][q] = gb[mi][q];

        // prefetch gates(t+1); poll flag at 8-step granule boundaries
        if (t + 1 < TT) {
            if (((t + 1) & (TF - 1)) == 0)
                wait_flag(&flg[(t + 1) >> 3]);
            const float* gnx = gptr + (size_t)(t + 1) * BB * 256;
            #pragma unroll
            for (int mi = 0; mi < 4; mi++)
                #pragma unroll
                for (int gg = 0; gg < 4; gg++) {
                    float2 v = *(const float2*)&gnx[(4 * tm + mi) * 256 + gg * 64 + 2 * tn];
                    gb[mi][gg * 2] = v.x; gb[mi][gg * 2 + 1] = v.y;
                }
        }

        // GEMM over k: h from warp registers via shfl
        #pragma unroll 8
        for (int k = 0; k < 64; k++) {
            const int r = k >> 1;
            float hv[4];
            #pragma unroll
            for (int mi = 0; mi < 4; mi++)
                hv[mi] = __shfl_sync(0xffffffffu,
                                     (k & 1) ? h1[mi] : h0[mi], r);
            #pragma unroll
            for (int gg = 0; gg < 4; gg++) {
                float2 w = *(const float2*)&sWhh[k * 256 + gg * 64 + 2 * tn];
                #pragma unroll
                for (int mi = 0; mi < 4; mi++) {
                    acc[mi][gg * 2 + 0] += hv[mi] * w.x;
                    acc[mi][gg * 2 + 1] += hv[mi] * w.y;
                }
            }
        }

        // cell update (gate order i, f, g, o)
        #pragma unroll
        for (int mi = 0; mi < 4; mi++) {
            {
                float ig = sigm(acc[mi][0]);
                float fg = sigm(acc[mi][2]);
                float gv = tanh_fast(acc[mi][4]);
                float og = sigm(acc[mi][6]);
                float cc = fg * c[mi][0] + ig * gv;
                c[mi][0] = cc;
                h0[mi] = og * tanh_fast(cc);
            }
            {
                float ig = sigm(acc[mi][1]);
                float fg = sigm(acc[mi][3]);
                float gv = tanh_fast(acc[mi][5]);
                float og = sigm(acc[mi][7]);
                float cc = fg * c[mi][1] + ig * gv;
                c[mi][1] = cc;
                h1[mi] = og * tanh_fast(cc);
            }
        }
    }

    // stage h_last to SMEM for the head GEMM
    #pragma unroll
    for (int mi = 0; mi < 4; mi++) {
        shl[(2 * tn + 0) * 33 + (4 * tm + mi)] = h0[mi];
        shl[(2 * tn + 1) * 33 + (4 * tm + mi)] = h1[mi];
    }
    __syncthreads();

    // head: pred[b][n][f] = leaky(h_last[b] . W_lin[f] + b_lin[f])
    for (int idx = tid; idx < BB * FUT; idx += 256) {
        int b = idx / FUT;
        int f = idx % FUT;
        float acc = sblin[f];
        #pragma unroll
        for (int u = 0; u < HL; u++)
            acc += shl[u * 33 + b] * sWlin[f * HL + u];
        float v = acc > 0.f ? acc : 0.01f * acc;
        out[((size_t)b * NH + n) * FUT + f] = v;
    }
}

// ---------------------------------------------------------------------------
extern "C" void kernel_launch(void* const* d_in, const int* in_sizes, int n_in,
                              void* d_out, int out_size)
{
    const float* data_meteo = (const float*)d_in[0];
    const float* data_hydro = (const float*)d_in[1];
    const int*   eh         = (const int*)  d_in[2];
    const int*   em         = (const int*)  d_in[3];
    const float* W_rel_m    = (const float*)d_in[4];
    const float* b_rel_m    = (const float*)d_in[5];
    const float* W_root_m   = (const float*)d_in[6];
    const float* W_rel_h    = (const float*)d_in[7];
    const float* b_rel_h    = (const float*)d_in[8];
    const float* W_root_h   = (const float*)d_in[9];
    const float* W_ih       = (const float*)d_in[10];
    const float* W_hh       = (const float*)d_in[11];
    const float* b_ih       = (const float*)d_in[12];
    const float* b_hh       = (const float*)d_in[13];
    const float* W_lin      = (const float*)d_in[14];
    const float* b_lin      = (const float*)d_in[15];

    const int Eh = in_sizes[2] / 2;
    const int Em = in_sizes[3] / 2;

    csr_kernel<<<1, 256>>>(eh, em, Eh, Em);

    gnn_kernel<<<(BB * TT) / TB, 256>>>(data_meteo, data_hydro,
                                        W_rel_m, b_rel_m, W_root_m,
                                        W_rel_h, b_rel_h, W_root_h);

    cudaFuncSetAttribute(fused_kernel,
                         cudaFuncAttributeMaxDynamicSharedMemorySize,
                         FUSED_BYTES);
    fused_kernel<<<NH + NH * (TT / TCB), 256, FUSED_BYTES>>>(
        W_ih, W_hh, b_ih, b_hh, W_lin, b_lin, (float*)d_out);
}

// round 14
// speedup vs baseline: 1.1677x; 1.1677x over previous
#include <cuda_runtime.h>
#include <cstdint>

#define BB   32
#define TT   336
#define NH   100
#define NM   150
#define FH   8
#define FM   16
#define HG   64
#define HL   64
#define FUT  24
#define TCB  48          // timesteps per producer block
#define TF   16          // timesteps per flag granule
#define NCK  (TT / TF)   // 21 flag granules
#define NPB  (TT / TCB)  // 7 producer blocks per node
#define TB   16          // graphs per gnn block

typedef unsigned long long u64;

#define FMA2(d, a, b) \
    asm("fma.rn.f32x2 %0, %1, %2, %0;" : "+l"(d) : "l"(a), "l"(b))
#define PACK2(d, v) \
    asm("mov.b64 %0, {%1, %1};" : "=l"(d) : "r"(__float_as_uint(v)))

// GNN output x: [n][t][b][hg]
__device__ float g_x[(size_t)NH * TT * BB * HG];
// Precomputed x-gates (+bias): [n][t][b][256]
__device__ float g_gates[(size_t)NH * TT * BB * 256];
// producer->consumer readiness flags, one per (node, 16-step granule)
__device__ int d_flag[NH * NCK];

// CSR edge structure (built once per launch, deterministic order)
__device__ int d_off_h[NH], d_deg_h[NH], d_src_h[512];
__device__ int d_off_m[NH], d_deg_m[NH], d_src_m[1024];

// ---------------------------------------------------------------------------
// Kernel A0: build CSR by target node; also zero the handshake flags.
// ---------------------------------------------------------------------------
__global__ void __launch_bounds__(256) csr_kernel(
    const int* __restrict__ eh, const int* __restrict__ em, int Eh, int Em)
{
    __shared__ int s_src[1024], s_tgt[1024];
    const int tid = threadIdx.x;

    for (int i = tid; i < NH * NCK; i += 256) d_flag[i] = 0;

    for (int i = tid; i < Eh; i += 256) { s_src[i] = eh[i]; s_tgt[i] = eh[Eh + i]; }
    __syncthreads();
    if (tid < NH) {
        int start = 0;
        for (int e = 0; e < Eh; e++) start += (s_tgt[e] < tid) ? 1 : 0;
        int p = start, cnt = 0;
        for (int e = 0; e < Eh; e++)
            if (s_tgt[e] == tid) { d_src_h[p++] = s_src[e]; cnt++; }
        d_off_h[tid] = start; d_deg_h[tid] = cnt;
    }
    __syncthreads();
    for (int i = tid; i < Em; i += 256) { s_src[i] = em[i]; s_tgt[i] = em[Em + i]; }
    __syncthreads();
    if (tid < NH) {
        int start = 0;
        for (int e = 0; e < Em; e++) start += (s_tgt[e] < tid) ? 1 : 0;
        int p = start, cnt = 0;
        for (int e = 0; e < Em; e++)
            if (s_tgt[e] == tid) { d_src_m[p++] = s_src[e]; cnt++; }
        d_off_m[tid] = start; d_deg_m[tid] = cnt;
    }
}

// ---------------------------------------------------------------------------
// Kernel A: hetero GraphConv, TB graphs per block, CSR gather. (R6, verified)
// ---------------------------------------------------------------------------
__global__ void __launch_bounds__(256) gnn_kernel(
    const float* __restrict__ xm_all, const float* __restrict__ xh_all,
    const float* __restrict__ Wrel_m, const float* __restrict__ brel_m,
    const float* __restrict__ Wroot_m,
    const float* __restrict__ Wrel_h, const float* __restrict__ brel_h,
    const float* __restrict__ Wroot_h)
{
    __shared__ float swh[FH * HG];
    __shared__ float swr[FH * HG];
    __shared__ float swm[FM * HG];
    __shared__ float sb[HG];
    __shared__ int soff_h[NH], sdeg_h[NH], ssrc_h[512];
    __shared__ int soff_m[NH], sdeg_m[NH], ssrc_m[1024];
    __shared__ float sxh[NH * FH];
    __shared__ float sxm[NM * FM];
    __shared__ float sah[NH * FH];
    __shared__ float sam[NH * FM];

    const int tid = threadIdx.x;

    for (int i = tid; i < HG * FH; i += 256) {
        int j = i / FH, k = i % FH;
        swh[k * HG + j] = 0.5f * Wrel_h[i];
        swr[k * HG + j] = 0.5f * (Wroot_h[i] + Wroot_m[i]);
    }
    for (int i = tid; i < HG * FM; i += 256) {
        int j = i / FM, k = i % FM;
        swm[k * HG + j] = 0.5f * Wrel_m[i];
    }
    for (int i = tid; i < HG; i += 256) sb[i] = 0.5f * (brel_h[i] + brel_m[i]);
    for (int i = tid; i < NH; i += 256) {
        soff_h[i] = d_off_h[i]; sdeg_h[i] = d_deg_h[i];
        soff_m[i] = d_off_m[i]; sdeg_m[i] = d_deg_m[i];
    }
    for (int i = tid; i < 512;  i += 256) ssrc_h[i] = d_src_h[i];
    for (int i = tid; i < 1024; i += 256) ssrc_m[i] = d_src_m[i];

    for (int gi = 0; gi < TB; gi++) {
        const int g = blockIdx.x * TB + gi;
        const float* xh = xh_all + (size_t)g * NH * FH;
        const float* xm = xm_all + (size_t)g * NM * FM;

        __syncthreads();
        for (int i = tid; i < NH * FH / 4; i += 256)
            *(float4*)&sxh[i * 4] = *(const float4*)&xh[i * 4];
        for (int i = tid; i < NM * FM / 4; i += 256)
            *(float4*)&sxm[i * 4] = *(const float4*)&xm[i * 4];
        __syncthreads();

        for (int idx = tid; idx < NH * FH; idx += 256) {
            int n = idx >> 3, k = idx & 7;
            int o = soff_h[n], d = sdeg_h[n];
            float s = 0.f;
            for (int e = 0; e < d; e++) s += sxh[ssrc_h[o + e] * FH + k];
            sah[idx] = s;
        }
        for (int idx = tid; idx < NH * FM; idx += 256) {
            int n = idx >> 4, k = idx & 15;
            int o = soff_m[n], d = sdeg_m[n];
            float s = 0.f;
            for (int e = 0; e < d; e++) s += sxm[ssrc_m[o + e] * FM + k];
            sam[idx] = s;
        }
        __syncthreads();

        const int t = g % TT;
        const int b = g / TT;
        for (int idx = tid; idx < NH * HG; idx += 256) {
            int n = idx >> 6, j = idx & 63;
            float acc = sb[j];
            #pragma unroll
            for (int k = 0; k < FH; k++)
                acc += sah[n * FH + k] * swh[k * HG + j]
                     + sxh[n * FH + k] * swr[k * HG + j];
            #pragma unroll
            for (int k = 0; k < FM; k++)
                acc += sam[n * FM + k] * swm[k * HG + j];
            float v = acc > 0.f ? acc : 0.01f * acc;
            g_x[(((size_t)n * TT + t) * BB + b) * HG + j] = v;
        }
    }
}

// ---------------------------------------------------------------------------
// FUSED kernel: blockIdx < NH  -> LSTM consumer (R12-exact)
//               blockIdx >= NH -> xgemm producer, 48 timesteps per block
//                                 (chunk-major), FFMA2 inner loop, publishes
//                                 a flag every 16 steps.
// ---------------------------------------------------------------------------
#define O_WHH 0
#define O_HL  16384
#define O_WL  (O_HL + 64*33)
#define O_BL  (O_WL + 24*64)
#define LS_FLOATS (O_BL + 32)
#define XG_SW 0
#define XG_SB 16384
#define XG_SX (16384 + 256)
#define XG_FLOATS (XG_SX + 64*33)
#define FUSED_FLOATS (LS_FLOATS > XG_FLOATS ? LS_FLOATS : XG_FLOATS)
#define FUSED_BYTES  (FUSED_FLOATS * 4)

__device__ __forceinline__ float sigm(float x) {
    return 1.0f / (1.0f + __expf(-x));
}
__device__ __forceinline__ float tanh_fast(float x) {
    float xc = fminf(fmaxf(x, -15.f), 15.f);
    float e = __expf(2.0f * xc);
    return (e - 1.0f) / (e + 1.0f);
}
__device__ __forceinline__ void wait_flag(const int* f) {
    int v;
    for (;;) {
        asm volatile("ld.acquire.gpu.s32 %0, [%1];" : "=r"(v) : "l"(f) : "memory");
        if (v) break;
        __nanosleep(200);
    }
}

__global__ void __launch_bounds__(256) fused_kernel(
    const float* __restrict__ W_ih, const float* __restrict__ W_hh,
    const float* __restrict__ b_ih, const float* __restrict__ b_hh,
    const float* __restrict__ W_lin, const float* __restrict__ b_lin,
    float* __restrict__ out)
{
    extern __shared__ float sm[];
    const int tid = threadIdx.x;

    if (blockIdx.x >= NH) {
        // -------- producer role: xgemm for (n, 48-step block), FFMA2 --------
        const int id = blockIdx.x - NH;
        const int cb = id / NH;          // 0..6, chunk-major: all nodes first
        const int n  = id % NH;
        const int t0 = cb * TCB;

        float* sW = sm + XG_SW;
        float* sb = sm + XG_SB;
        float* sx = sm + XG_SX;

        const float* w = W_ih + (size_t)n * 256 * 64;
        for (int i = tid; i < 16384; i += 256) {
            int j = i >> 6, k = i & 63;
            sW[k * 256 + j] = w[i];
        }
        sb[tid] = b_ih[n * 256 + tid] + b_hh[n * 256 + tid];

        const int tm = tid >> 5;
        const int tn = tid & 31;
        const int sb_b = tid >> 3;
        const int sb_k = (tid & 7) << 3;
        __syncthreads();

        // bias hoisted into registers for the whole 48-step block
        u64 binit[4];
        #pragma unroll
        for (int gg = 0; gg < 4; gg++)
            binit[gg] = *(const u64*)&sb[gg * 64 + 2 * tn];

        const float* xbase = g_x + ((size_t)n * TT + t0) * BB * HG;
        float* gbase = g_gates + ((size_t)n * TT + t0) * BB * 256;

        for (int tt = 0; tt < TCB; tt++) {
            const float* xt = xbase + (size_t)tt * BB * HG;
            float4 v0 = *(const float4*)&xt[sb_b * HG + sb_k];
            float4 v1 = *(const float4*)&xt[sb_b * HG + sb_k + 4];
            sx[(sb_k + 0) * 33 + sb_b] = v0.x;
            sx[(sb_k + 1) * 33 + sb_b] = v0.y;
            sx[(sb_k + 2) * 33 + sb_b] = v0.z;
            sx[(sb_k + 3) * 33 + sb_b] = v0.w;
            sx[(sb_k + 4) * 33 + sb_b] = v1.x;
            sx[(sb_k + 5) * 33 + sb_b] = v1.y;
            sx[(sb_k + 6) * 33 + sb_b] = v1.z;
            sx[(sb_k + 7) * 33 + sb_b] = v1.w;
            __syncthreads();

            u64 acc[16];   // [mi*4 + gg]
            #pragma unroll
            for (int mi = 0; mi < 4; mi++)
                #pragma unroll
                for (int gg = 0; gg < 4; gg++) acc[mi * 4 + gg] = binit[gg];

            #pragma unroll 4
            for (int k = 0; k < 64; k++) {
                u64 xx[4];
                #pragma unroll
                for (int mi = 0; mi < 4; mi++) {
                    float v = sx[k * 33 + 4 * tm + mi];
                    PACK2(xx[mi], v);
                }
                #pragma unroll
                for (int gg = 0; gg < 4; gg++) {
                    u64 wv = *(const u64*)&sW[k * 256 + gg * 64 + 2 * tn];
                    #pragma unroll
                    for (int mi = 0; mi < 4; mi++)
                        FMA2(acc[mi * 4 + gg], xx[mi], wv);
                }
            }

            float* gt = gbase + (size_t)tt * BB * 256;
            #pragma unroll
            for (int mi = 0; mi < 4; mi++)
                #pragma unroll
                for (int gg = 0; gg < 4; gg++)
                    *(u64*)&gt[(4 * tm + mi) * 256 + gg * 64 + 2 * tn] =
                        acc[mi * 4 + gg];
            __syncthreads();   // stores of steps <= tt complete block-wide

            // publish each 16-step granule as soon as it completes
            if ((tt & (TF - 1)) == TF - 1 && tid == 0) {
                __threadfence();
                atomicExch(&d_flag[n * NCK + (t0 + tt) / TF], 1);
            }
        }
        return;
    }

    // ------------------- consumer role: LSTM for node n (R12) ---------------
    const int n  = blockIdx.x;
    const int tm = tid >> 5;   // warp = batch group 4tm..4tm+3
    const int tn = tid & 31;   // lane = unit pair {2tn, 2tn+1}

    float* sWhh  = sm + O_WHH;   // [k][j] stride 256
    float* shl   = sm + O_HL;    // h_last [u][b] stride 33
    float* sWlin = sm + O_WL;
    float* sblin = sm + O_BL;

    const float* whh = W_hh + (size_t)n * 256 * 64;
    for (int i = tid; i < 16384; i += 256) {
        int j = i >> 6, k = i & 63;
        sWhh[k * 256 + j] = whh[i];
    }
    for (int i = tid; i < FUT * HL; i += 256) sWlin[i] = W_lin[i];
    if (tid < FUT) sblin[tid] = b_lin[tid];
    __syncthreads();

    const int* flg = &d_flag[n * NCK];

    float h0[4], h1[4], c[4][2];
    #pragma unroll
    for (int mi = 0; mi < 4; mi++) {
        h0[mi] = 0.f; h1[mi] = 0.f;
        c[mi][0] = 0.f; c[mi][1] = 0.f;
    }

    const float* gptr = g_gates + (size_t)n * TT * BB * 256;

    wait_flag(&flg[0]);
    float gb[4][8];
    #pragma unroll
    for (int mi = 0; mi < 4; mi++)
        #pragma unroll
        for (int gg = 0; gg < 4; gg++) {
            float2 v = *(const float2*)&gptr[(4 * tm + mi) * 256 + gg * 64 + 2 * tn];
            gb[mi][gg * 2] = v.x; gb[mi][gg * 2 + 1] = v.y;
        }

    for (int t = 0; t < TT; t++) {
        float acc[4][8];
        #pragma unroll
        for (int mi = 0; mi < 4; mi++)
            #pragma unroll
            for (int q = 0; q < 8; q++) acc[mi][q] = gb[mi][q];

        if (t + 1 < TT) {
            if (((t + 1) & (TF - 1)) == 0)
                wait_flag(&flg[(t + 1) >> 4]);
            const float* gnx = gptr + (size_t)(t + 1) * BB * 256;
            #pragma unroll
            for (int mi = 0; mi < 4; mi++)
                #pragma unroll
                for (int gg = 0; gg < 4; gg++) {
                    float2 v = *(const float2*)&gnx[(4 * tm + mi) * 256 + gg * 64 + 2 * tn];
                    gb[mi][gg * 2] = v.x; gb[mi][gg * 2 + 1] = v.y;
                }
        }

        #pragma unroll 8
        for (int k = 0; k < 64; k++) {
            const int r = k >> 1;
            float hv[4];
            #pragma unroll
            for (int mi = 0; mi < 4; mi++)
                hv[mi] = __shfl_sync(0xffffffffu,
                                     (k & 1) ? h1[mi] : h0[mi], r);
            #pragma unroll
            for (int gg = 0; gg < 4; gg++) {
                float2 w = *(const float2*)&sWhh[k * 256 + gg * 64 + 2 * tn];
                #pragma unroll
                for (int mi = 0; mi < 4; mi++) {
                    acc[mi][gg * 2 + 0] += hv[mi] * w.x;
                    acc[mi][gg * 2 + 1] += hv[mi] * w.y;
                }
            }
        }

        #pragma unroll
        for (int mi = 0; mi < 4; mi++) {
            {
                float ig = sigm(acc[mi][0]);
                float fg = sigm(acc[mi][2]);
                float gv = tanh_fast(acc[mi][4]);
                float og = sigm(acc[mi][6]);
                float cc = fg * c[mi][0] + ig * gv;
                c[mi][0] = cc;
                h0[mi] = og * tanh_fast(cc);
            }
            {
                float ig = sigm(acc[mi][1]);
                float fg = sigm(acc[mi][3]);
                float gv = tanh_fast(acc[mi][5]);
                float og = sigm(acc[mi][7]);
                float cc = fg * c[mi][1] + ig * gv;
                c[mi][1] = cc;
                h1[mi] = og * tanh_fast(cc);
            }
        }
    }

    #pragma unroll
    for (int mi = 0; mi < 4; mi++) {
        shl[(2 * tn + 0) * 33 + (4 * tm + mi)] = h0[mi];
        shl[(2 * tn + 1) * 33 + (4 * tm + mi)] = h1[mi];
    }
    __syncthreads();

    for (int idx = tid; idx < BB * FUT; idx += 256) {
        int b = idx / FUT;
        int f = idx % FUT;
        float acc = sblin[f];
        #pragma unroll
        for (int u = 0; u < HL; u++)
            acc += shl[u * 33 + b] * sWlin[f * HL + u];
        float v = acc > 0.f ? acc : 0.01f * acc;
        out[((size_t)b * NH + n) * FUT + f] = v;
    }
}

// ---------------------------------------------------------------------------
extern "C" void kernel_launch(void* const* d_in, const int* in_sizes, int n_in,
                              void* d_out, int out_size)
{
    const float* data_meteo = (const float*)d_in[0];
    const float* data_hydro = (const float*)d_in[1];
    const int*   eh         = (const int*)  d_in[2];
    const int*   em         = (const int*)  d_in[3];
    const float* W_rel_m    = (const float*)d_in[4];
    const float* b_rel_m    = (const float*)d_in[5];
    const float* W_root_m   = (const float*)d_in[6];
    const float* W_rel_h    = (const float*)d_in[7];
    const float* b_rel_h    = (const float*)d_in[8];
    const float* W_root_h   = (const float*)d_in[9];
    const float* W_ih       = (const float*)d_in[10];
    const float* W_hh       = (const float*)d_in[11];
    const float* b_ih       = (const float*)d_in[12];
    const float* b_hh       = (const float*)d_in[13];
    const float* W_lin      = (const float*)d_in[14];
    const float* b_lin      = (const float*)d_in[15];

    const int Eh = in_sizes[2] / 2;
    const int Em = in_sizes[3] / 2;

    csr_kernel<<<1, 256>>>(eh, em, Eh, Em);

    gnn_kernel<<<(BB * TT) / TB, 256>>>(data_meteo, data_hydro,
                                        W_rel_m, b_rel_m, W_root_m,
                                        W_rel_h, b_rel_h, W_root_h);

    cudaFuncSetAttribute(fused_kernel,
                         cudaFuncAttributeMaxDynamicSharedMemorySize,
                         FUSED_BYTES);
    fused_kernel<<<NH + NH * NPB, 256, FUSED_BYTES>>>(
        W_ih, W_hh, b_ih, b_hh, W_lin, b_lin, (float*)d_out);
}

// round 15
// speedup vs baseline: 1.2222x; 1.0467x over previous
#include <cuda_runtime.h>
#include <cstdint>

#define BB   32
#define TT   336
#define NH   100
#define NM   150
#define FH   8
#define FM   16
#define HG   64
#define HL   64
#define FUT  24
#define TCB  48          // timesteps per producer/gnn chunk
#define TF   16          // timesteps per flag granule
#define NCK  (TT / TF)   // 21 flag granules
#define NPB  (TT / TCB)  // 7 chunks
#define GPC  96          // gnn blocks per chunk (48 t * 32 b / 16 graphs)
#define GRP  (GPC + NH)  // 196: one chunk-group of gnn+xg blocks

typedef unsigned long long u64;

#define FMA2(d, a, b) \
    asm("fma.rn.f32x2 %0, %1, %2, %0;" : "+l"(d) : "l"(a), "l"(b))
#define PACK2(d, v) \
    asm("mov.b64 %0, {%1, %1};" : "=l"(d) : "r"(__float_as_uint(v)))

// GNN output x: [n][t][b][hg]
__device__ float g_x[(size_t)NH * TT * BB * HG];
// Precomputed x-gates (+bias): [n][t][b][256]
__device__ float g_gates[(size_t)NH * TT * BB * 256];
// xgemm->lstm readiness flags, one per (node, 16-step granule)
__device__ int d_flag[NH * NCK];
// gnn->xgemm chunk counters (target GPC)
__device__ int d_cnt[NPB];

// CSR edge structure (built once per launch, deterministic order)
__device__ int d_off_h[NH], d_deg_h[NH], d_src_h[512];
__device__ int d_off_m[NH], d_deg_m[NH], d_src_m[1024];

// ---------------------------------------------------------------------------
// Kernel A0: build CSR by target node; zero all handshake state.
// ---------------------------------------------------------------------------
__global__ void __launch_bounds__(256) csr_kernel(
    const int* __restrict__ eh, const int* __restrict__ em, int Eh, int Em)
{
    __shared__ int s_src[1024], s_tgt[1024];
    const int tid = threadIdx.x;

    for (int i = tid; i < NH * NCK; i += 256) d_flag[i] = 0;
    if (tid < NPB) d_cnt[tid] = 0;

    for (int i = tid; i < Eh; i += 256) { s_src[i] = eh[i]; s_tgt[i] = eh[Eh + i]; }
    __syncthreads();
    if (tid < NH) {
        int start = 0;
        for (int e = 0; e < Eh; e++) start += (s_tgt[e] < tid) ? 1 : 0;
        int p = start, cnt = 0;
        for (int e = 0; e < Eh; e++)
            if (s_tgt[e] == tid) { d_src_h[p++] = s_src[e]; cnt++; }
        d_off_h[tid] = start; d_deg_h[tid] = cnt;
    }
    __syncthreads();
    for (int i = tid; i < Em; i += 256) { s_src[i] = em[i]; s_tgt[i] = em[Em + i]; }
    __syncthreads();
    if (tid < NH) {
        int start = 0;
        for (int e = 0; e < Em; e++) start += (s_tgt[e] < tid) ? 1 : 0;
        int p = start, cnt = 0;
        for (int e = 0; e < Em; e++)
            if (s_tgt[e] == tid) { d_src_m[p++] = s_src[e]; cnt++; }
        d_off_m[tid] = start; d_deg_m[tid] = cnt;
    }
}

// ---------------------------------------------------------------------------
// FUSED pipeline kernel. Block schedule (blockIdx order):
//   [0,96)            gnn chunk 0        (pure work)
//   [96,196)          lstm consumers     (poll d_flag)
//   [196,296)         xgemm chunk 0      (poll d_cnt[0])
//   [296 + i*196 ...) gnn chunk i+1, then xgemm chunk i+1, i = 0..5
// gnn_ci publishes d_cnt[ci] (96 arrivals); xg_ci waits d_cnt[ci]==96, then
// produces gates and publishes d_flag per 16-step granule; consumers poll
// d_flag. Deadlock-free: gnn blocks never poll, and every polling block's
// dependencies precede it in schedule order.
// ---------------------------------------------------------------------------
// consumer smem layout (floats)
#define O_WHH 0
#define O_HL  16384
#define O_WL  (O_HL + 64*33)
#define O_BL  (O_WL + 24*64)
#define LS_FLOATS (O_BL + 32)
// xgemm producer smem layout
#define XG_SW 0
#define XG_SB 16384
#define XG_SX (16384 + 256)
#define XG_FLOATS (XG_SX + 64*33)
// gnn producer smem layout
#define G_WH  0                    // swh[512]
#define G_WR  512                  // swr[512]
#define G_WM  1024                 // swm[1024]
#define G_SB  2048                 // sb[64]
#define G_INT 2112                 // 1936 ints (CSR)
#define G_XH  4048                 // sxh[800]
#define G_XM  4848                 // sxm[2400]
#define G_AH  7248                 // sah[800]
#define G_AM  8048                 // sam[1600] -> 9648
#define GN_FLOATS 9680
#define FUSED_FLOATS (LS_FLOATS > XG_FLOATS ? LS_FLOATS : XG_FLOATS)
#define FUSED_BYTES  (FUSED_FLOATS * 4)

__device__ __forceinline__ float sigm(float x) {
    return 1.0f / (1.0f + __expf(-x));
}
__device__ __forceinline__ float tanh_fast(float x) {
    float xc = fminf(fmaxf(x, -15.f), 15.f);
    float e = __expf(2.0f * xc);
    return (e - 1.0f) / (e + 1.0f);
}
__device__ __forceinline__ void wait_flag(const int* f) {
    int v;
    for (;;) {
        asm volatile("ld.acquire.gpu.s32 %0, [%1];" : "=r"(v) : "l"(f) : "memory");
        if (v) break;
        __nanosleep(200);
    }
}
__device__ __forceinline__ void wait_cnt(const int* f, int target) {
    int v;
    for (;;) {
        asm volatile("ld.acquire.gpu.s32 %0, [%1];" : "=r"(v) : "l"(f) : "memory");
        if (v >= target) break;
        __nanosleep(200);
    }
}

__global__ void __launch_bounds__(256) fused_kernel(
    const float* __restrict__ xm_all, const float* __restrict__ xh_all,
    const float* __restrict__ Wrel_m, const float* __restrict__ brel_m,
    const float* __restrict__ Wroot_m,
    const float* __restrict__ Wrel_h, const float* __restrict__ brel_h,
    const float* __restrict__ Wroot_h,
    const float* __restrict__ W_ih, const float* __restrict__ W_hh,
    const float* __restrict__ b_ih, const float* __restrict__ b_hh,
    const float* __restrict__ W_lin, const float* __restrict__ b_lin,
    float* __restrict__ out)
{
    extern __shared__ float sm[];
    const int tid = threadIdx.x;

    // ---- role decode from the hand-crafted schedule ----
    const int bx = blockIdx.x;
    int role, ci = 0, sub;
    if (bx < GPC)               { role = 0; ci = 0; sub = bx; }          // gnn c0
    else if (bx < GPC + NH)     { role = 2;         sub = bx - GPC; }    // lstm
    else if (bx < GPC + 2 * NH) { role = 1; ci = 0; sub = bx - GPC - NH; } // xg c0
    else {
        int r = bx - (GPC + 2 * NH);
        ci = 1 + r / GRP;
        int w = r % GRP;
        if (w < GPC) { role = 0; sub = w; }
        else         { role = 1; sub = w - GPC; }
    }

    if (role == 0) {
        // =================== gnn producer: chunk ci, block sub ==============
        float* swh = sm + G_WH;
        float* swr = sm + G_WR;
        float* swm = sm + G_WM;
        float* sb  = sm + G_SB;
        int*   ip  = (int*)(sm + G_INT);
        int *soff_h = ip,        *sdeg_h = ip + 100,  *ssrc_h = ip + 200;
        int *soff_m = ip + 712,  *sdeg_m = ip + 812,  *ssrc_m = ip + 912;
        float* sxh = sm + G_XH;
        float* sxm = sm + G_XM;
        float* sah = sm + G_AH;
        float* sam = sm + G_AM;

        for (int i = tid; i < HG * FH; i += 256) {
            int j = i / FH, k = i % FH;
            swh[k * HG + j] = 0.5f * Wrel_h[i];
            swr[k * HG + j] = 0.5f * (Wroot_h[i] + Wroot_m[i]);
        }
        for (int i = tid; i < HG * FM; i += 256) {
            int j = i / FM, k = i % FM;
            swm[k * HG + j] = 0.5f * Wrel_m[i];
        }
        for (int i = tid; i < HG; i += 256)
            sb[i] = 0.5f * (brel_h[i] + brel_m[i]);
        for (int i = tid; i < NH; i += 256) {
            soff_h[i] = d_off_h[i]; sdeg_h[i] = d_deg_h[i];
            soff_m[i] = d_off_m[i]; sdeg_m[i] = d_deg_m[i];
        }
        for (int i = tid; i < 512;  i += 256) ssrc_h[i] = d_src_h[i];
        for (int i = tid; i < 1024; i += 256) ssrc_m[i] = d_src_m[i];

        // this block: timestep t_g, batches b0..b0+15
        const int t_g = ci * TCB + (sub >> 1);
        const int b0  = (sub & 1) * 16;

        for (int gi = 0; gi < 16; gi++) {
            const int b = b0 + gi;
            const int g = b * TT + t_g;
            const float* xh = xh_all + (size_t)g * NH * FH;
            const float* xm = xm_all + (size_t)g * NM * FM;

            __syncthreads();
            for (int i = tid; i < NH * FH / 4; i += 256)
                *(float4*)&sxh[i * 4] = *(const float4*)&xh[i * 4];
            for (int i = tid; i < NM * FM / 4; i += 256)
                *(float4*)&sxm[i * 4] = *(const float4*)&xm[i * 4];
            __syncthreads();

            for (int idx = tid; idx < NH * FH; idx += 256) {
                int n = idx >> 3, k = idx & 7;
                int o = soff_h[n], d = sdeg_h[n];
                float s = 0.f;
                for (int e = 0; e < d; e++) s += sxh[ssrc_h[o + e] * FH + k];
                sah[idx] = s;
            }
            for (int idx = tid; idx < NH * FM; idx += 256) {
                int n = idx >> 4, k = idx & 15;
                int o = soff_m[n], d = sdeg_m[n];
                float s = 0.f;
                for (int e = 0; e < d; e++) s += sxm[ssrc_m[o + e] * FM + k];
                sam[idx] = s;
            }
            __syncthreads();

            for (int idx = tid; idx < NH * HG; idx += 256) {
                int n = idx >> 6, j = idx & 63;
                float acc = sb[j];
                #pragma unroll
                for (int k = 0; k < FH; k++)
                    acc += sah[n * FH + k] * swh[k * HG + j]
                         + sxh[n * FH + k] * swr[k * HG + j];
                #pragma unroll
                for (int k = 0; k < FM; k++)
                    acc += sam[n * FM + k] * swm[k * HG + j];
                float v = acc > 0.f ? acc : 0.01f * acc;
                g_x[(((size_t)n * TT + t_g) * BB + b) * HG + j] = v;
            }
        }
        __syncthreads();
        if (tid == 0) {
            __threadfence();
            atomicAdd(&d_cnt[ci], 1);
        }
        return;
    }

    if (role == 1) {
        // ============ xgemm producer: (node sub, chunk ci), FFMA2 ===========
        const int n  = sub;
        const int t0 = ci * TCB;

        float* sW = sm + XG_SW;
        float* sb = sm + XG_SB;
        float* sx = sm + XG_SX;

        const float* w = W_ih + (size_t)n * 256 * 64;
        for (int i = tid; i < 16384; i += 256) {
            int j = i >> 6, k = i & 63;
            sW[k * 256 + j] = w[i];
        }
        sb[tid] = b_ih[n * 256 + tid] + b_hh[n * 256 + tid];

        const int tm = tid >> 5;
        const int tn = tid & 31;
        const int sb_b = tid >> 3;
        const int sb_k = (tid & 7) << 3;
        __syncthreads();

        u64 binit[4];
        #pragma unroll
        for (int gg = 0; gg < 4; gg++)
            binit[gg] = *(const u64*)&sb[gg * 64 + 2 * tn];

        // wait for this chunk's g_x to be fully produced
        wait_cnt(&d_cnt[ci], GPC);

        const float* xbase = g_x + ((size_t)n * TT + t0) * BB * HG;
        float* gbase = g_gates + ((size_t)n * TT + t0) * BB * 256;

        for (int tt = 0; tt < TCB; tt++) {
            const float* xt = xbase + (size_t)tt * BB * HG;
            float4 v0 = *(const float4*)&xt[sb_b * HG + sb_k];
            float4 v1 = *(const float4*)&xt[sb_b * HG + sb_k + 4];
            sx[(sb_k + 0) * 33 + sb_b] = v0.x;
            sx[(sb_k + 1) * 33 + sb_b] = v0.y;
            sx[(sb_k + 2) * 33 + sb_b] = v0.z;
            sx[(sb_k + 3) * 33 + sb_b] = v0.w;
            sx[(sb_k + 4) * 33 + sb_b] = v1.x;
            sx[(sb_k + 5) * 33 + sb_b] = v1.y;
            sx[(sb_k + 6) * 33 + sb_b] = v1.z;
            sx[(sb_k + 7) * 33 + sb_b] = v1.w;
            __syncthreads();

            u64 acc[16];
            #pragma unroll
            for (int mi = 0; mi < 4; mi++)
                #pragma unroll
                for (int gg = 0; gg < 4; gg++) acc[mi * 4 + gg] = binit[gg];

            #pragma unroll 4
            for (int k = 0; k < 64; k++) {
                u64 xx[4];
                #pragma unroll
                for (int mi = 0; mi < 4; mi++) {
                    float v = sx[k * 33 + 4 * tm + mi];
                    PACK2(xx[mi], v);
                }
                #pragma unroll
                for (int gg = 0; gg < 4; gg++) {
                    u64 wv = *(const u64*)&sW[k * 256 + gg * 64 + 2 * tn];
                    #pragma unroll
                    for (int mi = 0; mi < 4; mi++)
                        FMA2(acc[mi * 4 + gg], xx[mi], wv);
                }
            }

            float* gt = gbase + (size_t)tt * BB * 256;
            #pragma unroll
            for (int mi = 0; mi < 4; mi++)
                #pragma unroll
                for (int gg = 0; gg < 4; gg++)
                    *(u64*)&gt[(4 * tm + mi) * 256 + gg * 64 + 2 * tn] =
                        acc[mi * 4 + gg];
            __syncthreads();

            if ((tt & (TF - 1)) == TF - 1 && tid == 0) {
                __threadfence();
                atomicExch(&d_flag[n * NCK + (t0 + tt) / TF], 1);
            }
        }
        return;
    }

    // =================== consumer role: LSTM for node sub ===================
    const int n  = sub;
    const int tm = tid >> 5;   // warp = batch group 4tm..4tm+3
    const int tn = tid & 31;   // lane = unit pair {2tn, 2tn+1}

    float* sWhh  = sm + O_WHH;   // [k][j] stride 256
    float* shl   = sm + O_HL;    // h_last [u][b] stride 33
    float* sWlin = sm + O_WL;
    float* sblin = sm + O_BL;

    const float* whh = W_hh + (size_t)n * 256 * 64;
    for (int i = tid; i < 16384; i += 256) {
        int j = i >> 6, k = i & 63;
        sWhh[k * 256 + j] = whh[i];
    }
    for (int i = tid; i < FUT * HL; i += 256) sWlin[i] = W_lin[i];
    if (tid < FUT) sblin[tid] = b_lin[tid];
    __syncthreads();

    const int* flg = &d_flag[n * NCK];

    float h0[4], h1[4], c[4][2];
    #pragma unroll
    for (int mi = 0; mi < 4; mi++) {
        h0[mi] = 0.f; h1[mi] = 0.f;
        c[mi][0] = 0.f; c[mi][1] = 0.f;
    }

    const float* gptr = g_gates + (size_t)n * TT * BB * 256;

    wait_flag(&flg[0]);
    float gb[4][8];
    #pragma unroll
    for (int mi = 0; mi < 4; mi++)
        #pragma unroll
        for (int gg = 0; gg < 4; gg++) {
            float2 v = *(const float2*)&gptr[(4 * tm + mi) * 256 + gg * 64 + 2 * tn];
            gb[mi][gg * 2] = v.x; gb[mi][gg * 2 + 1] = v.y;
        }

    for (int t = 0; t < TT; t++) {
        float acc[4][8];
        #pragma unroll
        for (int mi = 0; mi < 4; mi++)
            #pragma unroll
            for (int q = 0; q < 8; q++) acc[mi][q] = gb[mi][q];

        if (t + 1 < TT) {
            if (((t + 1) & (TF - 1)) == 0)
                wait_flag(&flg[(t + 1) >> 4]);
            const float* gnx = gptr + (size_t)(t + 1) * BB * 256;
            #pragma unroll
            for (int mi = 0; mi < 4; mi++)
                #pragma unroll
                for (int gg = 0; gg < 4; gg++) {
                    float2 v = *(const float2*)&gnx[(4 * tm + mi) * 256 + gg * 64 + 2 * tn];
                    gb[mi][gg * 2] = v.x; gb[mi][gg * 2 + 1] = v.y;
                }
        }

        #pragma unroll 8
        for (int k = 0; k < 64; k++) {
            const int r = k >> 1;
            float hv[4];
            #pragma unroll
            for (int mi = 0; mi < 4; mi++)
                hv[mi] = __shfl_sync(0xffffffffu,
                                     (k & 1) ? h1[mi] : h0[mi], r);
            #pragma unroll
            for (int gg = 0; gg < 4; gg++) {
                float2 w = *(const float2*)&sWhh[k * 256 + gg * 64 + 2 * tn];
                #pragma unroll
                for (int mi = 0; mi < 4; mi++) {
                    acc[mi][gg * 2 + 0] += hv[mi] * w.x;
                    acc[mi][gg * 2 + 1] += hv[mi] * w.y;
                }
            }
        }

        #pragma unroll
        for (int mi = 0; mi < 4; mi++) {
            {
                float ig = sigm(acc[mi][0]);
                float fg = sigm(acc[mi][2]);
                float gv = tanh_fast(acc[mi][4]);
                float og = sigm(acc[mi][6]);
                float cc = fg * c[mi][0] + ig * gv;
                c[mi][0] = cc;
                h0[mi] = og * tanh_fast(cc);
            }
            {
                float ig = sigm(acc[mi][1]);
                float fg = sigm(acc[mi][3]);
                float gv = tanh_fast(acc[mi][5]);
                float og = sigm(acc[mi][7]);
                float cc = fg * c[mi][1] + ig * gv;
                c[mi][1] = cc;
                h1[mi] = og * tanh_fast(cc);
            }
        }
    }

    #pragma unroll
    for (int mi = 0; mi < 4; mi++) {
        shl[(2 * tn + 0) * 33 + (4 * tm + mi)] = h0[mi];
        shl[(2 * tn + 1) * 33 + (4 * tm + mi)] = h1[mi];
    }
    __syncthreads();

    for (int idx = tid; idx < BB * FUT; idx += 256) {
        int b = idx / FUT;
        int f = idx % FUT;
        float acc = sblin[f];
        #pragma unroll
        for (int u = 0; u < HL; u++)
            acc += shl[u * 33 + b] * sWlin[f * HL + u];
        float v = acc > 0.f ? acc : 0.01f * acc;
        out[((size_t)b * NH + n) * FUT + f] = v;
    }
}

// ---------------------------------------------------------------------------
extern "C" void kernel_launch(void* const* d_in, const int* in_sizes, int n_in,
                              void* d_out, int out_size)
{
    const float* data_meteo = (const float*)d_in[0];
    const float* data_hydro = (const float*)d_in[1];
    const int*   eh         = (const int*)  d_in[2];
    const int*   em         = (const int*)  d_in[3];
    const float* W_rel_m    = (const float*)d_in[4];
    const float* b_rel_m    = (const float*)d_in[5];
    const float* W_root_m   = (const float*)d_in[6];
    const float* W_rel_h    = (const float*)d_in[7];
    const float* b_rel_h    = (const float*)d_in[8];
    const float* W_root_h   = (const float*)d_in[9];
    const float* W_ih       = (const float*)d_in[10];
    const float* W_hh       = (const float*)d_in[11];
    const float* b_ih       = (const float*)d_in[12];
    const float* b_hh       = (const float*)d_in[13];
    const float* W_lin      = (const float*)d_in[14];
    const float* b_lin      = (const float*)d_in[15];

    const int Eh = in_sizes[2] / 2;
    const int Em = in_sizes[3] / 2;

    csr_kernel<<<1, 256>>>(eh, em, Eh, Em);

    cudaFuncSetAttribute(fused_kernel,
                         cudaFuncAttributeMaxDynamicSharedMemorySize,
                         FUSED_BYTES);
    const int grid = GPC + 2 * NH + (NPB - 1) * GRP;   // 296 + 6*196 = 1472
    fused_kernel<<<grid, 256, FUSED_BYTES>>>(
        data_meteo, data_hydro,
        W_rel_m, b_rel_m, W_root_m,
        W_rel_h, b_rel_h, W_root_h,
        W_ih, W_hh, b_ih, b_hh, W_lin, b_lin, (float*)d_out);
}

// round 16
// speedup vs baseline: 1.3003x; 1.0639x over previous
#include <cuda_runtime.h>
#include <cstdint>

#define BB   32
#define TT   336
#define NH   100
#define NM   150
#define FH   8
#define FM   16
#define HG   64
#define HL   64
#define FUT  24
#define TCB  48          // timesteps per producer/gnn chunk
#define TF   16          // timesteps per flag granule
#define NCK  (TT / TF)   // 21 flag granules
#define NPB  (TT / TCB)  // 7 chunks
#define GPC  96          // gnn blocks per chunk
#define GRP  (GPC + NH)  // 196: one chunk-group of gnn+xg blocks

typedef unsigned long long u64;

#define FMA2(d, a, b) \
    asm("fma.rn.f32x2 %0, %1, %2, %0;" : "+l"(d) : "l"(a), "l"(b))
#define PACK2(d, v) \
    asm("mov.b64 %0, {%1, %1};" : "=l"(d) : "r"(__float_as_uint(v)))
#define UNPACK2(lo, hi, x) \
    asm("mov.b64 {%0, %1}, %2;" : "=f"(lo), "=f"(hi) : "l"(x))

// GNN output x: [n][t][b][hg]
__device__ float g_x[(size_t)NH * TT * BB * HG];
// Precomputed x-gates (+bias): [n][t][b][256]
__device__ float g_gates[(size_t)NH * TT * BB * 256];
// xgemm->lstm readiness flags, one per (node, 16-step granule)
__device__ int d_flag[NH * NCK];
// gnn->xgemm chunk counters (target GPC)
__device__ int d_cnt[NPB];

// CSR edge structure (built once per launch, deterministic order)
__device__ int d_off_h[NH], d_deg_h[NH], d_src_h[512];
__device__ int d_off_m[NH], d_deg_m[NH], d_src_m[1024];

// ---------------------------------------------------------------------------
// Kernel A0: build CSR by target node; zero all handshake state.
// ---------------------------------------------------------------------------
__global__ void __launch_bounds__(256) csr_kernel(
    const int* __restrict__ eh, const int* __restrict__ em, int Eh, int Em)
{
    __shared__ int s_src[1024], s_tgt[1024];
    const int tid = threadIdx.x;

    for (int i = tid; i < NH * NCK; i += 256) d_flag[i] = 0;
    if (tid < NPB) d_cnt[tid] = 0;

    for (int i = tid; i < Eh; i += 256) { s_src[i] = eh[i]; s_tgt[i] = eh[Eh + i]; }
    __syncthreads();
    if (tid < NH) {
        int start = 0;
        for (int e = 0; e < Eh; e++) start += (s_tgt[e] < tid) ? 1 : 0;
        int p = start, cnt = 0;
        for (int e = 0; e < Eh; e++)
            if (s_tgt[e] == tid) { d_src_h[p++] = s_src[e]; cnt++; }
        d_off_h[tid] = start; d_deg_h[tid] = cnt;
    }
    __syncthreads();
    for (int i = tid; i < Em; i += 256) { s_src[i] = em[i]; s_tgt[i] = em[Em + i]; }
    __syncthreads();
    if (tid < NH) {
        int start = 0;
        for (int e = 0; e < Em; e++) start += (s_tgt[e] < tid) ? 1 : 0;
        int p = start, cnt = 0;
        for (int e = 0; e < Em; e++)
            if (s_tgt[e] == tid) { d_src_m[p++] = s_src[e]; cnt++; }
        d_off_m[tid] = start; d_deg_m[tid] = cnt;
    }
}

// ---------------------------------------------------------------------------
// FUSED pipeline kernel (schedule identical to R15).
// ---------------------------------------------------------------------------
#define O_WHH 0
#define O_HL  16384
#define O_WL  (O_HL + 64*33)
#define O_BL  (O_WL + 24*64)
#define LS_FLOATS (O_BL + 32)
#define XG_SW 0
#define XG_SB 16384
#define XG_SX (16384 + 256)
#define XG_FLOATS (XG_SX + 64*33)
#define G_WH  0
#define G_WR  512
#define G_WM  1024
#define G_SB  2048
#define G_INT 2112
#define G_XH  4048
#define G_XM  4848
#define G_AH  7248
#define G_AM  8048
#define FUSED_FLOATS (LS_FLOATS > XG_FLOATS ? LS_FLOATS : XG_FLOATS)
#define FUSED_BYTES  (FUSED_FLOATS * 4)

__device__ __forceinline__ float sigm(float x) {
    return 1.0f / (1.0f + __expf(-x));
}
__device__ __forceinline__ float tanh_fast(float x) {
    float xc = fminf(fmaxf(x, -15.f), 15.f);
    float e = __expf(2.0f * xc);
    return (e - 1.0f) / (e + 1.0f);
}
__device__ __forceinline__ void wait_flag(const int* f) {
    int v;
    for (;;) {
        asm volatile("ld.acquire.gpu.s32 %0, [%1];" : "=r"(v) : "l"(f) : "memory");
        if (v) break;
        __nanosleep(200);
    }
}
__device__ __forceinline__ void wait_cnt(const int* f, int target) {
    int v;
    for (;;) {
        asm volatile("ld.acquire.gpu.s32 %0, [%1];" : "=r"(v) : "l"(f) : "memory");
        if (v >= target) break;
        __nanosleep(200);
    }
}

__global__ void __launch_bounds__(256) fused_kernel(
    const float* __restrict__ xm_all, const float* __restrict__ xh_all,
    const float* __restrict__ Wrel_m, const float* __restrict__ brel_m,
    const float* __restrict__ Wroot_m,
    const float* __restrict__ Wrel_h, const float* __restrict__ brel_h,
    const float* __restrict__ Wroot_h,
    const float* __restrict__ W_ih, const float* __restrict__ W_hh,
    const float* __restrict__ b_ih, const float* __restrict__ b_hh,
    const float* __restrict__ W_lin, const float* __restrict__ b_lin,
    float* __restrict__ out)
{
    extern __shared__ float sm[];
    const int tid = threadIdx.x;

    // ---- role decode from the hand-crafted schedule ----
    const int bx = blockIdx.x;
    int role, ci = 0, sub;
    if (bx < GPC)               { role = 0; ci = 0; sub = bx; }
    else if (bx < GPC + NH)     { role = 2;         sub = bx - GPC; }
    else if (bx < GPC + 2 * NH) { role = 1; ci = 0; sub = bx - GPC - NH; }
    else {
        int r = bx - (GPC + 2 * NH);
        ci = 1 + r / GRP;
        int w = r % GRP;
        if (w < GPC) { role = 0; sub = w; }
        else         { role = 1; sub = w - GPC; }
    }

    if (role == 0) {
        // =================== gnn producer: chunk ci, block sub ==============
        float* swh = sm + G_WH;
        float* swr = sm + G_WR;
        float* swm = sm + G_WM;
        float* sb  = sm + G_SB;
        int*   ip  = (int*)(sm + G_INT);
        int *soff_h = ip,        *sdeg_h = ip + 100,  *ssrc_h = ip + 200;
        int *soff_m = ip + 712,  *sdeg_m = ip + 812,  *ssrc_m = ip + 912;
        float* sxh = sm + G_XH;
        float* sxm = sm + G_XM;
        float* sah = sm + G_AH;
        float* sam = sm + G_AM;

        for (int i = tid; i < HG * FH; i += 256) {
            int j = i / FH, k = i % FH;
            swh[k * HG + j] = 0.5f * Wrel_h[i];
            swr[k * HG + j] = 0.5f * (Wroot_h[i] + Wroot_m[i]);
        }
        for (int i = tid; i < HG * FM; i += 256) {
            int j = i / FM, k = i % FM;
            swm[k * HG + j] = 0.5f * Wrel_m[i];
        }
        for (int i = tid; i < HG; i += 256)
            sb[i] = 0.5f * (brel_h[i] + brel_m[i]);
        for (int i = tid; i < NH; i += 256) {
            soff_h[i] = d_off_h[i]; sdeg_h[i] = d_deg_h[i];
            soff_m[i] = d_off_m[i]; sdeg_m[i] = d_deg_m[i];
        }
        for (int i = tid; i < 512;  i += 256) ssrc_h[i] = d_src_h[i];
        for (int i = tid; i < 1024; i += 256) ssrc_m[i] = d_src_m[i];

        const int t_g = ci * TCB + (sub >> 1);
        const int b0  = (sub & 1) * 16;

        for (int gi = 0; gi < 16; gi++) {
            const int b = b0 + gi;
            const int g = b * TT + t_g;
            const float* xh = xh_all + (size_t)g * NH * FH;
            const float* xm = xm_all + (size_t)g * NM * FM;

            __syncthreads();
            for (int i = tid; i < NH * FH / 4; i += 256)
                *(float4*)&sxh[i * 4] = *(const float4*)&xh[i * 4];
            for (int i = tid; i < NM * FM / 4; i += 256)
                *(float4*)&sxm[i * 4] = *(const float4*)&xm[i * 4];
            __syncthreads();

            for (int idx = tid; idx < NH * FH; idx += 256) {
                int n = idx >> 3, k = idx & 7;
                int o = soff_h[n], d = sdeg_h[n];
                float s = 0.f;
                for (int e = 0; e < d; e++) s += sxh[ssrc_h[o + e] * FH + k];
                sah[idx] = s;
            }
            for (int idx = tid; idx < NH * FM; idx += 256) {
                int n = idx >> 4, k = idx & 15;
                int o = soff_m[n], d = sdeg_m[n];
                float s = 0.f;
                for (int e = 0; e < d; e++) s += sxm[ssrc_m[o + e] * FM + k];
                sam[idx] = s;
            }
            __syncthreads();

            for (int idx = tid; idx < NH * HG; idx += 256) {
                int n = idx >> 6, j = idx & 63;
                float acc = sb[j];
                #pragma unroll
                for (int k = 0; k < FH; k++)
                    acc += sah[n * FH + k] * swh[k * HG + j]
                         + sxh[n * FH + k] * swr[k * HG + j];
                #pragma unroll
                for (int k = 0; k < FM; k++)
                    acc += sam[n * FM + k] * swm[k * HG + j];
                float v = acc > 0.f ? acc : 0.01f * acc;
                g_x[(((size_t)n * TT + t_g) * BB + b) * HG + j] = v;
            }
        }
        __syncthreads();
        if (tid == 0) {
            __threadfence();
            atomicAdd(&d_cnt[ci], 1);
        }
        return;
    }

    if (role == 1) {
        // ============ xgemm producer: (node sub, chunk ci), FFMA2 ===========
        const int n  = sub;
        const int t0 = ci * TCB;

        float* sW = sm + XG_SW;
        float* sb = sm + XG_SB;
        float* sx = sm + XG_SX;

        const float* w = W_ih + (size_t)n * 256 * 64;
        for (int i = tid; i < 16384; i += 256) {
            int j = i >> 6, k = i & 63;
            sW[k * 256 + j] = w[i];
        }
        sb[tid] = b_ih[n * 256 + tid] + b_hh[n * 256 + tid];

        const int tm = tid >> 5;
        const int tn = tid & 31;
        const int sb_b = tid >> 3;
        const int sb_k = (tid & 7) << 3;
        __syncthreads();

        u64 binit[4];
        #pragma unroll
        for (int gg = 0; gg < 4; gg++)
            binit[gg] = *(const u64*)&sb[gg * 64 + 2 * tn];

        wait_cnt(&d_cnt[ci], GPC);

        const float* xbase = g_x + ((size_t)n * TT + t0) * BB * HG;
        float* gbase = g_gates + ((size_t)n * TT + t0) * BB * 256;

        for (int tt = 0; tt < TCB; tt++) {
            const float* xt = xbase + (size_t)tt * BB * HG;
            float4 v0 = *(const float4*)&xt[sb_b * HG + sb_k];
            float4 v1 = *(const float4*)&xt[sb_b * HG + sb_k + 4];
            sx[(sb_k + 0) * 33 + sb_b] = v0.x;
            sx[(sb_k + 1) * 33 + sb_b] = v0.y;
            sx[(sb_k + 2) * 33 + sb_b] = v0.z;
            sx[(sb_k + 3) * 33 + sb_b] = v0.w;
            sx[(sb_k + 4) * 33 + sb_b] = v1.x;
            sx[(sb_k + 5) * 33 + sb_b] = v1.y;
            sx[(sb_k + 6) * 33 + sb_b] = v1.z;
            sx[(sb_k + 7) * 33 + sb_b] = v1.w;
            __syncthreads();

            u64 acc[16];
            #pragma unroll
            for (int mi = 0; mi < 4; mi++)
                #pragma unroll
                for (int gg = 0; gg < 4; gg++) acc[mi * 4 + gg] = binit[gg];

            #pragma unroll 4
            for (int k = 0; k < 64; k++) {
                u64 xx[4];
                #pragma unroll
                for (int mi = 0; mi < 4; mi++) {
                    float v = sx[k * 33 + 4 * tm + mi];
                    PACK2(xx[mi], v);
                }
                #pragma unroll
                for (int gg = 0; gg < 4; gg++) {
                    u64 wv = *(const u64*)&sW[k * 256 + gg * 64 + 2 * tn];
                    #pragma unroll
                    for (int mi = 0; mi < 4; mi++)
                        FMA2(acc[mi * 4 + gg], xx[mi], wv);
                }
            }

            float* gt = gbase + (size_t)tt * BB * 256;
            #pragma unroll
            for (int mi = 0; mi < 4; mi++)
                #pragma unroll
                for (int gg = 0; gg < 4; gg++)
                    *(u64*)&gt[(4 * tm + mi) * 256 + gg * 64 + 2 * tn] =
                        acc[mi * 4 + gg];
            __syncthreads();

            if ((tt & (TF - 1)) == TF - 1 && tid == 0) {
                __threadfence();
                atomicExch(&d_flag[n * NCK + (t0 + tt) / TF], 1);
            }
        }
        return;
    }

    // =================== consumer role: LSTM for node sub, FFMA2 ============
    const int n  = sub;
    const int tm = tid >> 5;   // warp = batch group 4tm..4tm+3
    const int tn = tid & 31;   // lane = unit pair {2tn, 2tn+1}

    float* sWhh  = sm + O_WHH;   // [k][j] stride 256
    float* shl   = sm + O_HL;    // h_last [u][b] stride 33
    float* sWlin = sm + O_WL;
    float* sblin = sm + O_BL;

    const float* whh = W_hh + (size_t)n * 256 * 64;
    for (int i = tid; i < 16384; i += 256) {
        int j = i >> 6, k = i & 63;
        sWhh[k * 256 + j] = whh[i];
    }
    for (int i = tid; i < FUT * HL; i += 256) sWlin[i] = W_lin[i];
    if (tid < FUT) sblin[tid] = b_lin[tid];
    __syncthreads();

    const int* flg = &d_flag[n * NCK];

    float h0[4], h1[4], c[4][2];
    #pragma unroll
    for (int mi = 0; mi < 4; mi++) {
        h0[mi] = 0.f; h1[mi] = 0.f;
        c[mi][0] = 0.f; c[mi][1] = 0.f;
    }

    const float* gptr = g_gates + (size_t)n * TT * BB * 256;

    // packed gate prefetch (u64 = {unit 2tn, unit 2tn+1})
    wait_flag(&flg[0]);
    u64 gb[4][4];
    #pragma unroll
    for (int mi = 0; mi < 4; mi++)
        #pragma unroll
        for (int gg = 0; gg < 4; gg++)
            gb[mi][gg] = *(const u64*)&gptr[(4 * tm + mi) * 256 + gg * 64 + 2 * tn];

    for (int t = 0; t < TT; t++) {
        u64 acc[4][4];
        #pragma unroll
        for (int mi = 0; mi < 4; mi++)
            #pragma unroll
            for (int gg = 0; gg < 4; gg++) acc[mi][gg] = gb[mi][gg];

        if (t + 1 < TT) {
            if (((t + 1) & (TF - 1)) == 0)
                wait_flag(&flg[(t + 1) >> 4]);
            const float* gnx = gptr + (size_t)(t + 1) * BB * 256;
            #pragma unroll
            for (int mi = 0; mi < 4; mi++)
                #pragma unroll
                for (int gg = 0; gg < 4; gg++)
                    gb[mi][gg] = *(const u64*)&gnx[(4 * tm + mi) * 256 + gg * 64 + 2 * tn];
        }

        // packed GEMM over k: h via shfl, weights as LDS.64, FFMA2
        #pragma unroll 8
        for (int k = 0; k < 64; k++) {
            const int r = k >> 1;
            u64 hx[4];
            #pragma unroll
            for (int mi = 0; mi < 4; mi++) {
                float hv = __shfl_sync(0xffffffffu,
                                       (k & 1) ? h1[mi] : h0[mi], r);
                PACK2(hx[mi], hv);
            }
            #pragma unroll
            for (int gg = 0; gg < 4; gg++) {
                u64 wv = *(const u64*)&sWhh[k * 256 + gg * 64 + 2 * tn];
                #pragma unroll
                for (int mi = 0; mi < 4; mi++)
                    FMA2(acc[mi][gg], hx[mi], wv);
            }
        }

        // cell update (gate order i, f, g, o)
        #pragma unroll
        for (int mi = 0; mi < 4; mi++) {
            float iv[2], fv[2], gv[2], ov[2];
            UNPACK2(iv[0], iv[1], acc[mi][0]);
            UNPACK2(fv[0], fv[1], acc[mi][1]);
            UNPACK2(gv[0], gv[1], acc[mi][2]);
            UNPACK2(ov[0], ov[1], acc[mi][3]);
            {
                float ig = sigm(iv[0]);
                float fg = sigm(fv[0]);
                float gv0 = tanh_fast(gv[0]);
                float og = sigm(ov[0]);
                float cc = fg * c[mi][0] + ig * gv0;
                c[mi][0] = cc;
                h0[mi] = og * tanh_fast(cc);
            }
            {
                float ig = sigm(iv[1]);
                float fg = sigm(fv[1]);
                float gv1 = tanh_fast(gv[1]);
                float og = sigm(ov[1]);
                float cc = fg * c[mi][1] + ig * gv1;
                c[mi][1] = cc;
                h1[mi] = og * tanh_fast(cc);
            }
        }
    }

    #pragma unroll
    for (int mi = 0; mi < 4; mi++) {
        shl[(2 * tn + 0) * 33 + (4 * tm + mi)] = h0[mi];
        shl[(2 * tn + 1) * 33 + (4 * tm + mi)] = h1[mi];
    }
    __syncthreads();

    for (int idx = tid; idx < BB * FUT; idx += 256) {
        int b = idx / FUT;
        int f = idx % FUT;
        float acc = sblin[f];
        #pragma unroll
        for (int u = 0; u < HL; u++)
            acc += shl[u * 33 + b] * sWlin[f * HL + u];
        float v = acc > 0.f ? acc : 0.01f * acc;
        out[((size_t)b * NH + n) * FUT + f] = v;
    }
}

// ---------------------------------------------------------------------------
extern "C" void kernel_launch(void* const* d_in, const int* in_sizes, int n_in,
                              void* d_out, int out_size)
{
    const float* data_meteo = (const float*)d_in[0];
    const float* data_hydro = (const float*)d_in[1];
    const int*   eh         = (const int*)  d_in[2];
    const int*   em         = (const int*)  d_in[3];
    const float* W_rel_m    = (const float*)d_in[4];
    const float* b_rel_m    = (const float*)d_in[5];
    const float* W_root_m   = (const float*)d_in[6];
    const float* W_rel_h    = (const float*)d_in[7];
    const float* b_rel_h    = (const float*)d_in[8];
    const float* W_root_h   = (const float*)d_in[9];
    const float* W_ih       = (const float*)d_in[10];
    const float* W_hh       = (const float*)d_in[11];
    const float* b_ih       = (const float*)d_in[12];
    const float* b_hh       = (const float*)d_in[13];
    const float* W_lin      = (const float*)d_in[14];
    const float* b_lin      = (const float*)d_in[15];

    const int Eh = in_sizes[2] / 2;
    const int Em = in_sizes[3] / 2;

    csr_kernel<<<1, 256>>>(eh, em, Eh, Em);

    cudaFuncSetAttribute(fused_kernel,
                         cudaFuncAttributeMaxDynamicSharedMemorySize,
                         FUSED_BYTES);
    const int grid = GPC + 2 * NH + (NPB - 1) * GRP;   // 1472
    fused_kernel<<<grid, 256, FUSED_BYTES>>>(
        data_meteo, data_hydro,
        W_rel_m, b_rel_m, W_root_m,
        W_rel_h, b_rel_h, W_root_h,
        W_ih, W_hh, b_ih, b_hh, W_lin, b_lin, (float*)d_out);
}